// round 9
// baseline (speedup 1.0000x reference)
#include <cuda_runtime.h>
#include <math.h>

#ifndef M_PI
#define M_PI 3.14159265358979323846
#endif

#define MM 4096
#define NN 4096
#define RNK 10
#define PD 12           // padded D row stride (floats) for 16B-aligned LDS.128
#define TRI 55          // 10*11/2 packed lower triangle
#define NWRD 128        // 4096/32 mask words per row
#define GSEG 32         // row segments for gram
#define GROWS (MM/GSEG) // 128 rows per gram block
#define ASEG 32         // row segments for IRLS passes
#define AROWS (MM/ASEG) // 128 rows per IRLS block
#define N_LAYERS 3

typedef unsigned long long u64;

// ---------------- device scratch (static: no allocation APIs) ----------------
__device__ float    g_U[MM*RNK];
__device__ float    g_V[RNK*NN];
__device__ float    g_XT[(size_t)MM*NN];          // 64 MB
__device__ unsigned g_mb [MM*NWRD];               // mask bits of X (row-major)
__device__ unsigned g_mbT[NN*NWRD];               // mask bits of X^T
__device__ float    g_nobs_col[NN];
__device__ float    g_nobs_row[MM];
__device__ float    g_Gpart[GSEG*TRI*NN];         // 28.8 MB partial Grams
__device__ float    g_G[TRI*NN];                  // reduced Gram
__device__ float    g_Ginv[TRI*NN];               // inv Gram, layout [tri][j]
__device__ float    g_Spart[ASEG*NN];             // psi^2 partials
__device__ float    g_Rpart0[ASEG*RNK*NN];        // rhs partials iter0 [seg][k][j]
__device__ float    g_Rpart1[ASEG*RNK*NN];        // rhs partials iter1
__device__ float    g_beta1[RNK*NN];              // beta after iter0, layout [k][j]
__device__ float    g_sigma[NN];
__device__ float    g_sc[8];                      // alpha, c, lamda, mu, sigma0

// ---------------- f32x2 packed helpers ----------------
__device__ __forceinline__ u64 pk(float a, float b){
  u64 r; asm("mov.b64 %0, {%1, %2};" : "=l"(r) : "f"(a), "f"(b)); return r;
}
__device__ __forceinline__ void upk(u64 v, float& a, float& b){
  asm("mov.b64 {%0, %1}, %2;" : "=f"(a), "=f"(b) : "l"(v));
}
__device__ __forceinline__ u64 fma2(u64 a, u64 b, u64 c){
  u64 d; asm("fma.rn.f32x2 %0, %1, %2, %3;" : "=l"(d) : "l"(a), "l"(b), "l"(c)); return d;
}
__device__ __forceinline__ u64 mul2(u64 a, u64 b){
  u64 d; asm("mul.rn.f32x2 %0, %1, %2;" : "=l"(d) : "l"(a), "l"(b)); return d;
}

__device__ __forceinline__ int triat(int a, int q){
  return (a>=q) ? (a*(a+1)/2+q) : (q*(q+1)/2+a);
}

// ---------------- scalar prep ----------------
__global__ void k_scalars(const float* c, const float* lam, const float* mu, const float* sg){
  double cd = (double)c[0];
  double t1 = erf(cd * 0.7071067811865475244);
  double chi3 = t1 - sqrt(2.0/M_PI)*cd*exp(-0.5*cd*cd);
  double alpha = 0.5*cd*cd*(1.0 - t1) + 0.5*chi3;
  g_sc[0] = (float)alpha;
  g_sc[1] = c[0];
  g_sc[2] = lam[0];
  g_sc[3] = mu[0];
  g_sc[4] = sg[0];
}

__global__ void k_copyUV(const float* __restrict__ U, const float* __restrict__ V){
  int t = blockIdx.x*256 + threadIdx.x;
  if (t < MM*RNK){ g_U[t] = U[t]; g_V[t] = V[t]; }
}

// -------- fused transpose X -> g_XT + bitpack of both orientations ----------
__global__ void k_transpose(const float* __restrict__ src){
  __shared__ float tile[32][33];
  int bx = blockIdx.x*32, by = blockIdx.y*32;
  int tx = threadIdx.x, ty = threadIdx.y;
  #pragma unroll
  for (int yo=0; yo<32; yo+=8){
    float v = src[(size_t)(by+ty+yo)*NN + bx+tx];
    tile[ty+yo][tx] = v;
    unsigned w = __ballot_sync(0xffffffffu, v != 0.0f);
    if (tx==0) g_mb[(by+ty+yo)*NWRD + (bx>>5)] = w;
  }
  __syncthreads();
  #pragma unroll
  for (int yo=0; yo<32; yo+=8){
    float v = tile[tx][ty+yo];
    g_XT[(size_t)(bx+ty+yo)*NN + by+tx] = v;
    unsigned w = __ballot_sync(0xffffffffu, v != 0.0f);
    if (tx==0) g_mbT[(bx+ty+yo)*NWRD + (by>>5)] = w;
  }
}

// ---------------- nobs: warp-per-row, uint4 loads ----------------
__global__ void k_nobs(){
  int t = blockIdx.x*8 + threadIdx.y;     // [0, 8192)
  int lane = threadIdx.x;
  int j = t & (NN-1);
  const unsigned* b = (t < NN) ? g_mbT : g_mb;
  uint4 w = *reinterpret_cast<const uint4*>(&b[j*NWRD + lane*4]);
  int s = __popc(w.x)+__popc(w.y)+__popc(w.z)+__popc(w.w);
  #pragma unroll
  for (int o=16;o;o>>=1) s += __shfl_xor_sync(0xffffffffu, s, o);
  if (lane==0){
    if (t < NN) g_nobs_col[j] = (float)s; else g_nobs_row[j] = (float)s;
  }
}

// --------- masked Gram, triangle split 2-way, LDS.128 d loads ----------------
// grid (64, GSEG), block (32,4). wq = bx*2 + (ty>>1); half = ty&1.
__global__ void __launch_bounds__(128) k_gram(int step){
  __shared__ __align__(16) u64 sD[(GROWS/2)*RNK];   // 5 KB packed row pairs
  const float* D       = step ? g_V : g_U;
  const int sDr        = step ? 1   : RNK;
  const int sDc        = step ? NN  : 1;
  const unsigned* bits = step ? g_mbT : g_mb;
  int tx = threadIdx.x, ty = threadIdx.y;
  int tid = ty*32 + tx;
  int wq = blockIdx.x*2 + (ty>>1);     // [0,128)
  int half = ty & 1;
  int base = blockIdx.y * GROWS;
  for (int t = tid; t < (GROWS/2)*RNK; t += 128){
    int k = t >> 6, rp = t & 63;       // GROWS/2 = 64
    int r0 = base + 2*rp;
    sD[rp*RNK + k] = pk(D[r0*sDr + k*sDc], D[(r0+1)*sDr + k*sDc]);
  }
  __syncthreads();
  int j = wq*32 + tx;
  float* out = g_Gpart + blockIdx.y*(TRI*NN);
  const unsigned* bp = bits + (size_t)base*NWRD + wq;
  u64 z = pk(0.f, 0.f);
  if (half == 0){
    u64 acc[28];
    #pragma unroll
    for (int t=0;t<28;t++) acc[t]=z;
    #pragma unroll 2
    for (int rp=0; rp<GROWS/2; rp++){
      unsigned w0 = bp[0];
      unsigned w1 = bp[NWRD];
      bp += 2*NWRD;
      u64 mm = pk((float)((w0>>tx)&1u), (float)((w1>>tx)&1u));
      const ulonglong2* dq = reinterpret_cast<const ulonglong2*>(&sD[rp*RNK]);
      u64 d[8];
      ulonglong2 q0 = dq[0], q1 = dq[1], q2 = dq[2], q3 = dq[3];
      d[0]=q0.x; d[1]=q0.y; d[2]=q1.x; d[3]=q1.y;
      d[4]=q2.x; d[5]=q2.y; d[6]=q3.x; d[7]=q3.y;
      #pragma unroll
      for (int k=0;k<7;k++){
        u64 dm = mul2(d[k], mm);
        #pragma unroll
        for (int l=0;l<=k;l++)
          acc[k*(k+1)/2+l] = fma2(dm, d[l], acc[k*(k+1)/2+l]);
      }
    }
    #pragma unroll
    for (int t=0;t<28;t++){
      float a,b; upk(acc[t],a,b);
      out[t*NN + j] = a + b;
    }
  } else {
    u64 acc[27];
    #pragma unroll
    for (int t=0;t<27;t++) acc[t]=z;
    #pragma unroll 2
    for (int rp=0; rp<GROWS/2; rp++){
      unsigned w0 = bp[0];
      unsigned w1 = bp[NWRD];
      bp += 2*NWRD;
      u64 mm = pk((float)((w0>>tx)&1u), (float)((w1>>tx)&1u));
      const ulonglong2* dq = reinterpret_cast<const ulonglong2*>(&sD[rp*RNK]);
      u64 d[RNK];
      ulonglong2 q0 = dq[0], q1 = dq[1], q2 = dq[2], q3 = dq[3], q4 = dq[4];
      d[0]=q0.x; d[1]=q0.y; d[2]=q1.x; d[3]=q1.y;
      d[4]=q2.x; d[5]=q2.y; d[6]=q3.x; d[7]=q3.y;
      d[8]=q4.x; d[9]=q4.y;
      #pragma unroll
      for (int k=7;k<RNK;k++){
        u64 dm = mul2(d[k], mm);
        #pragma unroll
        for (int l=0;l<=k;l++)
          acc[k*(k+1)/2+l-28] = fma2(dm, d[l], acc[k*(k+1)/2+l-28]);
      }
    }
    #pragma unroll
    for (int t=0;t<27;t++){
      float a,b; upk(acc[t],a,b);
      out[(t+28)*NN + j] = a + b;
    }
  }
}

// ---------------- reduce Gram partials ----------------
__global__ void k_gred(){
  int e = blockIdx.x*256 + threadIdx.x;   // [0, TRI*NN)
  float s = 0.f;
  #pragma unroll
  for (int seg=0; seg<GSEG; seg++) s += g_Gpart[seg*(TRI*NN) + e];
  g_G[e] = s;
}

// ---------------- 10x10 SPD inverse via packed in-place Cholesky ----------------
__global__ void __launch_bounds__(64) k_ginv(){
  int j = blockIdx.x*64 + threadIdx.x;
  float A[TRI];
  #pragma unroll
  for (int t=0;t<TRI;t++) A[t] = g_G[t*NN + j];
  #pragma unroll
  for (int k=0;k<RNK;k++){
    float s = A[k*(k+1)/2+k];
    #pragma unroll
    for (int m2=0;m2<k;m2++){ float v=A[k*(k+1)/2+m2]; s -= v*v; }
    float lkk = sqrtf(s);
    A[k*(k+1)/2+k]=lkk;
    float inv = 1.0f/lkk;
    #pragma unroll
    for (int i=k+1;i<RNK;i++){
      float t = A[i*(i+1)/2+k];
      #pragma unroll
      for (int m2=0;m2<k;m2++) t -= A[i*(i+1)/2+m2]*A[k*(k+1)/2+m2];
      A[i*(i+1)/2+k]=t*inv;
    }
  }
  #pragma unroll
  for (int jj=0;jj<RNK;jj++){
    A[jj*(jj+1)/2+jj] = 1.0f/A[jj*(jj+1)/2+jj];
    #pragma unroll
    for (int i=jj+1;i<RNK;i++){
      float s=0.f;
      #pragma unroll
      for (int m2=jj;m2<i;m2++) s += A[i*(i+1)/2+m2]*A[m2*(m2+1)/2+jj];
      A[i*(i+1)/2+jj] = -s / A[i*(i+1)/2+i];
    }
  }
  #pragma unroll
  for (int a=0;a<RNK;a++){
    #pragma unroll
    for (int b=0;b<=a;b++){
      float s=0.f;
      #pragma unroll
      for (int m2=a;m2<RNK;m2++) s += A[m2*(m2+1)/2+a]*A[m2*(m2+1)/2+b];
      g_Ginv[(a*(a+1)/2+b)*NN + j] = s;
    }
  }
}

// ---- shared helper: load D chunk into padded smem (stride PD, 16B aligned) --
__device__ __forceinline__ void load_D_pad(float* sD, const float* D,
                                           int base, int sDr, int sDc, int tid){
  for (int t=tid; t<AROWS*RNK; t+=256){
    int k = t >> 7, r = t & (AROWS-1);
    sD[r*PD+k] = D[(base+r)*sDr + k*sDc];
  }
}

// ---------------- IRLS pass A: psi^2 partials ----------------
// grid (NN/64, ASEG), block (64,4). One column per thread; d via LDS.128.
__global__ void __launch_bounds__(256) k_psiA(const float* __restrict__ Xin, int step, int it){
  __shared__ __align__(16) float sD[AROWS*PD];   // 6 KB
  __shared__ float sS[4][65];
  const float* Y    = step ? g_XT : Xin;
  const float* D    = step ? g_V : g_U;
  const int sDr     = step ? 1   : RNK;
  const int sDc     = step ? NN  : 1;
  const float* beta = step ? g_U : g_V;
  const int sBj     = step ? RNK : 1;
  const int sBk     = step ? 1   : NN;
  int tx=threadIdx.x, ty=threadIdx.y, tid=ty*64+tx;
  int j = blockIdx.x*64 + tx;
  int base = blockIdx.y * AROWS;
  load_D_pad(sD, D, base, sDr, sDc, tid);
  __syncthreads();
  float nb[RNK];
  if (it){
    #pragma unroll
    for (int k=0;k<RNK;k++) nb[k] = -g_beta1[k*NN + j];
  } else {
    #pragma unroll
    for (int k=0;k<RNK;k++) nb[k] = -beta[j*sBj + k*sBk];
  }
  float cc = g_sc[1];
  float sig = it ? g_sigma[j] : g_sc[4];
  float invs = 1.0f/sig;
  float S = 0.f;
  #pragma unroll 8
  for (int r=ty; r<AROWS; r+=4){
    float x = Y[(size_t)(base+r)*NN + j];
    const float* dp = &sD[r*PD];
    float4 d0 = *reinterpret_cast<const float4*>(dp);
    float4 d1 = *reinterpret_cast<const float4*>(dp+4);
    float2 d2 = *reinterpret_cast<const float2*>(dp+8);
    float rr = x;
    rr = fmaf(d0.x, nb[0], rr); rr = fmaf(d0.y, nb[1], rr);
    rr = fmaf(d0.z, nb[2], rr); rr = fmaf(d0.w, nb[3], rr);
    rr = fmaf(d1.x, nb[4], rr); rr = fmaf(d1.y, nb[5], rr);
    rr = fmaf(d1.z, nb[6], rr); rr = fmaf(d1.w, nb[7], rr);
    rr = fmaf(d2.x, nb[8], rr); rr = fmaf(d2.y, nb[9], rr);
    rr = (x==0.f) ? 0.f : rr;
    float p = fminf(cc, fmaxf(-cc, rr*invs));
    S = fmaf(p,p,S);
  }
  sS[ty][tx] = S;
  __syncthreads();
  if (ty==0){
    float tot = sS[0][tx]+sS[1][tx]+sS[2][tx]+sS[3][tx];
    g_Spart[blockIdx.y*NN + j] = tot;
  }
}

// ---------------- IRLS pass B: inline sigma + rhs partials ----------------
__global__ void __launch_bounds__(256) k_rhsB(const float* __restrict__ Xin, int step, int it){
  __shared__ __align__(16) float sD[AROWS*PD];   // 6 KB
  __shared__ float sR[RNK][4][65];               // 10.4 KB
  const float* Y    = step ? g_XT : Xin;
  const float* D    = step ? g_V : g_U;
  const int sDr     = step ? 1   : RNK;
  const int sDc     = step ? NN  : 1;
  const float* beta = step ? g_U : g_V;
  const int sBj     = step ? RNK : 1;
  const int sBk     = step ? 1   : NN;
  const float* nobs = step ? g_nobs_row : g_nobs_col;
  int tx=threadIdx.x, ty=threadIdx.y, tid=ty*64+tx;
  int j = blockIdx.x*64 + tx;
  int base = blockIdx.y * AROWS;
  load_D_pad(sD, D, base, sDr, sDc, tid);
  __syncthreads();
  float nb[RNK];
  if (it){
    #pragma unroll
    for (int k=0;k<RNK;k++) nb[k] = -g_beta1[k*NN + j];
  } else {
    #pragma unroll
    for (int k=0;k<RNK;k++) nb[k] = -beta[j*sBj + k*sBk];
  }
  // inline sigma update: sigma_new = sigma_prev * tau^lamda
  float SA=0.f;
  #pragma unroll
  for (int s=0;s<ASEG;s++) SA += g_Spart[s*NN + j];
  float sp = it ? g_sigma[j] : g_sc[4];
  float tau = sqrtf(SA) / sqrtf(2.0f*nobs[j]*g_sc[0]);
  float sig = sp * powf(tau, g_sc[2]);
  if (it==0 && blockIdx.y==0 && ty==0) g_sigma[j] = sig;
  float cs = g_sc[1]*sig;

  float rhs[RNK];
  #pragma unroll
  for (int k=0;k<RNK;k++) rhs[k]=0.f;
  #pragma unroll 4
  for (int r=ty; r<AROWS; r+=4){
    float x = Y[(size_t)(base+r)*NN + j];
    const float* dp = &sD[r*PD];
    float4 d0 = *reinterpret_cast<const float4*>(dp);
    float4 d1 = *reinterpret_cast<const float4*>(dp+4);
    float2 d2 = *reinterpret_cast<const float2*>(dp+8);
    float rr = x;
    rr = fmaf(d0.x, nb[0], rr); rr = fmaf(d0.y, nb[1], rr);
    rr = fmaf(d0.z, nb[2], rr); rr = fmaf(d0.w, nb[3], rr);
    rr = fmaf(d1.x, nb[4], rr); rr = fmaf(d1.y, nb[5], rr);
    rr = fmaf(d1.z, nb[6], rr); rr = fmaf(d1.w, nb[7], rr);
    rr = fmaf(d2.x, nb[8], rr); rr = fmaf(d2.y, nb[9], rr);
    rr = (x==0.f) ? 0.f : rr;
    float w = fminf(cs, fmaxf(-cs, rr));
    rhs[0] = fmaf(d0.x, w, rhs[0]); rhs[1] = fmaf(d0.y, w, rhs[1]);
    rhs[2] = fmaf(d0.z, w, rhs[2]); rhs[3] = fmaf(d0.w, w, rhs[3]);
    rhs[4] = fmaf(d1.x, w, rhs[4]); rhs[5] = fmaf(d1.y, w, rhs[5]);
    rhs[6] = fmaf(d1.z, w, rhs[6]); rhs[7] = fmaf(d1.w, w, rhs[7]);
    rhs[8] = fmaf(d2.x, w, rhs[8]); rhs[9] = fmaf(d2.y, w, rhs[9]);
  }
  #pragma unroll
  for (int k=0;k<RNK;k++) sR[k][ty][tx] = rhs[k];
  __syncthreads();
  if (ty==0){
    float* Rout = it ? g_Rpart1 : g_Rpart0;
    #pragma unroll
    for (int k=0;k<RNK;k++){
      float s = sR[k][0][tx]+sR[k][1][tx]+sR[k][2][tx]+sR[k][3][tx];
      Rout[(blockIdx.y*RNK + k)*NN + j] = s;
    }
  }
}

// -------- beta1 = beta0 + mu*Ginv*rhs0 (materialized once, layout [k][j]) ----
__global__ void __launch_bounds__(128) k_beta1(int step){
  int j = blockIdx.x*128 + threadIdx.x;
  const float* beta = step ? g_U : g_V;
  const int sBj = step ? RNK : 1;
  const int sBk = step ? 1   : NN;
  float rr[RNK];
  #pragma unroll
  for (int k=0;k<RNK;k++){
    float s=0.f;
    #pragma unroll
    for (int seg=0;seg<ASEG;seg++) s += g_Rpart0[(seg*RNK + k)*NN + j];
    rr[k]=s;
  }
  float muv = g_sc[3];
  #pragma unroll
  for (int a=0;a<RNK;a++){
    float s=0.f;
    #pragma unroll
    for (int q=0;q<RNK;q++)
      s = fmaf(g_Ginv[triat(a,q)*NN + j], rr[q], s);
    g_beta1[a*NN + j] = beta[j*sBj + a*sBk] + muv*s;
  }
}

// -------- final beta for the step: beta2 = beta1 + mu*Ginv*rhs1 --------------
__global__ void __launch_bounds__(128) k_beta2(int step){
  int j = blockIdx.x*128 + threadIdx.x;
  float* beta = step ? g_U : g_V;
  const int sBj = step ? RNK : 1;
  const int sBk = step ? 1   : NN;
  float rr[RNK];
  #pragma unroll
  for (int k=0;k<RNK;k++){
    float s=0.f;
    #pragma unroll
    for (int seg=0;seg<ASEG;seg++) s += g_Rpart1[(seg*RNK + k)*NN + j];
    rr[k]=s;
  }
  float muv = g_sc[3];
  #pragma unroll
  for (int a=0;a<RNK;a++){
    float s=0.f;
    #pragma unroll
    for (int q=0;q<RNK;q++)
      s = fmaf(g_Ginv[triat(a,q)*NN + j], rr[q], s);
    beta[j*sBj + a*sBk] = g_beta1[a*NN + j] + muv*s;
  }
}

// ---------------- final output: U @ V (float4 over columns) ----------------
__global__ void k_out(float* __restrict__ out){
  int e = blockIdx.x*256 + threadIdx.x;   // group of 4 outputs
  int i = e >> 10;
  int j4 = (e & 1023) * 4;
  float4 s = make_float4(0.f,0.f,0.f,0.f);
  #pragma unroll
  for (int k=0;k<RNK;k++){
    float u = g_U[i*RNK+k];
    float4 v = *reinterpret_cast<const float4*>(&g_V[k*NN + j4]);
    s.x = fmaf(u, v.x, s.x);
    s.y = fmaf(u, v.y, s.y);
    s.z = fmaf(u, v.z, s.z);
    s.w = fmaf(u, v.w, s.w);
  }
  reinterpret_cast<float4*>(out)[e] = s;
}

// ---------------- host driver (graph-capturable: kernel launches only) ----------------
extern "C" void kernel_launch(void* const* d_in, const int* in_sizes, int n_in,
                              void* d_out, int out_size){
  const float *U=0, *V=0, *X=0, *pc=0, *plam=0, *pmu=0, *psg=0;
  int nuv=0, nsc=0;
  for (int i=0;i<n_in;i++){
    if (in_sizes[i] == MM*NN) X = (const float*)d_in[i];
    else if (in_sizes[i] == MM*RNK){ if (nuv==0) U=(const float*)d_in[i]; else V=(const float*)d_in[i]; nuv++; }
    else if (in_sizes[i] == 1){
      if      (nsc==0) pc  =(const float*)d_in[i];
      else if (nsc==1) plam=(const float*)d_in[i];
      else if (nsc==2) pmu =(const float*)d_in[i];
      else if (nsc==3) psg =(const float*)d_in[i];
      nsc++;
    }
  }
  float* out = (float*)d_out;

  k_scalars<<<1,1>>>(pc, plam, pmu, psg);                        // launch 0
  k_copyUV<<<(MM*RNK + 255)/256, 256>>>(U, V);                   // launch 1
  {
    dim3 g(NN/32, MM/32), b(32,8);
    k_transpose<<<g,b>>>(X);                                     // launch 2
  }

  dim3 ggrid(64, GSEG), gblk(32,4);
  dim3 igrid(NN/64, ASEG), iblk(64,4);
  dim3 ngrid(8192/8), nblk(32,8);
  for (int layer=0; layer<N_LAYERS; layer++){
    for (int step=0; step<2; step++){   // 0: V-step, 1: U-step
      k_gram<<<ggrid, gblk>>>(step);                             // first = launch 3 (profiled)
      if (layer==0 && step==0) k_nobs<<<ngrid, nblk>>>();
      k_gred<<<(TRI*NN)/256, 256>>>();
      k_ginv<<<NN/64, 64>>>();
      k_psiA<<<igrid, iblk>>>(X, step, 0);
      k_rhsB<<<igrid, iblk>>>(X, step, 0);
      k_beta1<<<NN/128, 128>>>(step);
      k_psiA<<<igrid, iblk>>>(X, step, 1);
      k_rhsB<<<igrid, iblk>>>(X, step, 1);
      k_beta2<<<NN/128, 128>>>(step);
    }
  }
  k_out<<<(MM*NN/4)/256, 256>>>(out);
}

// round 10
// speedup vs baseline: 1.5736x; 1.5736x over previous
#include <cuda_runtime.h>
#include <math.h>

#ifndef M_PI
#define M_PI 3.14159265358979323846
#endif

#define MM 4096
#define NN 4096
#define RNK 10
#define PDU 12          // padded dup-packed D row stride in u64 (96B, 16B aligned)
#define TRI 55          // 10*11/2 packed lower triangle
#define NWRD 128        // 4096/32 mask words per row
#define GSEG 32         // row segments for gram
#define GROWS (MM/GSEG) // 128 rows per gram block
#define ASEG 32         // row segments for IRLS passes
#define AROWS (MM/ASEG) // 128 rows per IRLS block
#define N_LAYERS 3

typedef unsigned long long u64;

// ---------------- device scratch (static: no allocation APIs) ----------------
__device__ float    g_U[MM*RNK];
__device__ float    g_V[RNK*NN];
__device__ float    g_XT[(size_t)MM*NN];          // 64 MB
__device__ unsigned g_mb [MM*NWRD];               // mask bits of X (row-major)
__device__ unsigned g_mbT[NN*NWRD];               // mask bits of X^T
__device__ float    g_nobs_col[NN];
__device__ float    g_nobs_row[MM];
__device__ float    g_Gpart[GSEG*TRI*NN];         // 28.8 MB partial Grams
__device__ float    g_G[TRI*NN];                  // reduced Gram
__device__ float    g_Ginv[TRI*NN];               // inv Gram, layout [tri][j]
__device__ float    g_Spart[ASEG*NN];             // psi^2 partials
__device__ float    g_Rpart0[ASEG*RNK*NN];        // rhs partials iter0 [seg][k][j]
__device__ float    g_Rpart1[ASEG*RNK*NN];        // rhs partials iter1
__device__ float    g_beta1[RNK*NN];              // beta after iter0, layout [k][j]
__device__ float    g_sigma[NN];
__device__ float    g_sc[8];                      // alpha, c, lamda, mu, sigma0

// ---------------- f32x2 packed helpers ----------------
__device__ __forceinline__ u64 pk(float a, float b){
  u64 r; asm("mov.b64 %0, {%1, %2};" : "=l"(r) : "f"(a), "f"(b)); return r;
}
__device__ __forceinline__ void upk(u64 v, float& a, float& b){
  asm("mov.b64 {%0, %1}, %2;" : "=f"(a), "=f"(b) : "l"(v));
}
__device__ __forceinline__ u64 fma2(u64 a, u64 b, u64 c){
  u64 d; asm("fma.rn.f32x2 %0, %1, %2, %3;" : "=l"(d) : "l"(a), "l"(b), "l"(c)); return d;
}
__device__ __forceinline__ u64 mul2(u64 a, u64 b){
  u64 d; asm("mul.rn.f32x2 %0, %1, %2;" : "=l"(d) : "l"(a), "l"(b)); return d;
}

__device__ __forceinline__ int triat(int a, int q){
  return (a>=q) ? (a*(a+1)/2+q) : (q*(q+1)/2+a);
}

// ---------------- scalar prep ----------------
__global__ void k_scalars(const float* c, const float* lam, const float* mu, const float* sg){
  double cd = (double)c[0];
  double t1 = erf(cd * 0.7071067811865475244);
  double chi3 = t1 - sqrt(2.0/M_PI)*cd*exp(-0.5*cd*cd);
  double alpha = 0.5*cd*cd*(1.0 - t1) + 0.5*chi3;
  g_sc[0] = (float)alpha;
  g_sc[1] = c[0];
  g_sc[2] = lam[0];
  g_sc[3] = mu[0];
  g_sc[4] = sg[0];
}

__global__ void k_copyUV(const float* __restrict__ U, const float* __restrict__ V){
  int t = blockIdx.x*256 + threadIdx.x;
  if (t < MM*RNK){ g_U[t] = U[t]; g_V[t] = V[t]; }
}

// -------- fused transpose X -> g_XT + bitpack of both orientations ----------
__global__ void k_transpose(const float* __restrict__ src){
  __shared__ float tile[32][33];
  int bx = blockIdx.x*32, by = blockIdx.y*32;
  int tx = threadIdx.x, ty = threadIdx.y;
  #pragma unroll
  for (int yo=0; yo<32; yo+=8){
    float v = src[(size_t)(by+ty+yo)*NN + bx+tx];
    tile[ty+yo][tx] = v;
    unsigned w = __ballot_sync(0xffffffffu, v != 0.0f);
    if (tx==0) g_mb[(by+ty+yo)*NWRD + (bx>>5)] = w;
  }
  __syncthreads();
  #pragma unroll
  for (int yo=0; yo<32; yo+=8){
    float v = tile[tx][ty+yo];
    g_XT[(size_t)(bx+ty+yo)*NN + by+tx] = v;
    unsigned w = __ballot_sync(0xffffffffu, v != 0.0f);
    if (tx==0) g_mbT[(bx+ty+yo)*NWRD + (by>>5)] = w;
  }
}

// ---------------- nobs: warp-per-row, uint4 loads ----------------
__global__ void k_nobs(){
  int t = blockIdx.x*8 + threadIdx.y;     // [0, 8192)
  int lane = threadIdx.x;
  int j = t & (NN-1);
  const unsigned* b = (t < NN) ? g_mbT : g_mb;
  uint4 w = *reinterpret_cast<const uint4*>(&b[j*NWRD + lane*4]);
  int s = __popc(w.x)+__popc(w.y)+__popc(w.z)+__popc(w.w);
  #pragma unroll
  for (int o=16;o;o>>=1) s += __shfl_xor_sync(0xffffffffu, s, o);
  if (lane==0){
    if (t < NN) g_nobs_col[j] = (float)s; else g_nobs_row[j] = (float)s;
  }
}

// --------- masked Gram, triangle split 2-way, LDS.128 d loads ----------------
// grid (64, GSEG), block (32,4). wq = bx*2 + (ty>>1); half = ty&1.
__global__ void __launch_bounds__(128) k_gram(int step){
  __shared__ __align__(16) u64 sD[(GROWS/2)*RNK];   // 5 KB packed row pairs
  const float* D       = step ? g_V : g_U;
  const int sDr        = step ? 1   : RNK;
  const int sDc        = step ? NN  : 1;
  const unsigned* bits = step ? g_mbT : g_mb;
  int tx = threadIdx.x, ty = threadIdx.y;
  int tid = ty*32 + tx;
  int wq = blockIdx.x*2 + (ty>>1);     // [0,128)
  int half = ty & 1;
  int base = blockIdx.y * GROWS;
  for (int t = tid; t < (GROWS/2)*RNK; t += 128){
    int k = t >> 6, rp = t & 63;       // GROWS/2 = 64
    int r0 = base + 2*rp;
    sD[rp*RNK + k] = pk(D[r0*sDr + k*sDc], D[(r0+1)*sDr + k*sDc]);
  }
  __syncthreads();
  int j = wq*32 + tx;
  float* out = g_Gpart + blockIdx.y*(TRI*NN);
  const unsigned* bp = bits + (size_t)base*NWRD + wq;
  u64 z = pk(0.f, 0.f);
  if (half == 0){
    u64 acc[28];
    #pragma unroll
    for (int t=0;t<28;t++) acc[t]=z;
    #pragma unroll 2
    for (int rp=0; rp<GROWS/2; rp++){
      unsigned w0 = bp[0];
      unsigned w1 = bp[NWRD];
      bp += 2*NWRD;
      u64 mm = pk((float)((w0>>tx)&1u), (float)((w1>>tx)&1u));
      const ulonglong2* dq = reinterpret_cast<const ulonglong2*>(&sD[rp*RNK]);
      u64 d[8];
      ulonglong2 q0 = dq[0], q1 = dq[1], q2 = dq[2], q3 = dq[3];
      d[0]=q0.x; d[1]=q0.y; d[2]=q1.x; d[3]=q1.y;
      d[4]=q2.x; d[5]=q2.y; d[6]=q3.x; d[7]=q3.y;
      #pragma unroll
      for (int k=0;k<7;k++){
        u64 dm = mul2(d[k], mm);
        #pragma unroll
        for (int l=0;l<=k;l++)
          acc[k*(k+1)/2+l] = fma2(dm, d[l], acc[k*(k+1)/2+l]);
      }
    }
    #pragma unroll
    for (int t=0;t<28;t++){
      float a,b; upk(acc[t],a,b);
      out[t*NN + j] = a + b;
    }
  } else {
    u64 acc[27];
    #pragma unroll
    for (int t=0;t<27;t++) acc[t]=z;
    #pragma unroll 2
    for (int rp=0; rp<GROWS/2; rp++){
      unsigned w0 = bp[0];
      unsigned w1 = bp[NWRD];
      bp += 2*NWRD;
      u64 mm = pk((float)((w0>>tx)&1u), (float)((w1>>tx)&1u));
      const ulonglong2* dq = reinterpret_cast<const ulonglong2*>(&sD[rp*RNK]);
      u64 d[RNK];
      ulonglong2 q0 = dq[0], q1 = dq[1], q2 = dq[2], q3 = dq[3], q4 = dq[4];
      d[0]=q0.x; d[1]=q0.y; d[2]=q1.x; d[3]=q1.y;
      d[4]=q2.x; d[5]=q2.y; d[6]=q3.x; d[7]=q3.y;
      d[8]=q4.x; d[9]=q4.y;
      #pragma unroll
      for (int k=7;k<RNK;k++){
        u64 dm = mul2(d[k], mm);
        #pragma unroll
        for (int l=0;l<=k;l++)
          acc[k*(k+1)/2+l-28] = fma2(dm, d[l], acc[k*(k+1)/2+l-28]);
      }
    }
    #pragma unroll
    for (int t=0;t<27;t++){
      float a,b; upk(acc[t],a,b);
      out[(t+28)*NN + j] = a + b;
    }
  }
}

// ---------------- reduce Gram partials ----------------
__global__ void k_gred(){
  int e = blockIdx.x*256 + threadIdx.x;   // [0, TRI*NN)
  float s = 0.f;
  #pragma unroll
  for (int seg=0; seg<GSEG; seg++) s += g_Gpart[seg*(TRI*NN) + e];
  g_G[e] = s;
}

// ---------------- 10x10 SPD inverse via packed in-place Cholesky ----------------
__global__ void __launch_bounds__(64) k_ginv(){
  int j = blockIdx.x*64 + threadIdx.x;
  float A[TRI];
  #pragma unroll
  for (int t=0;t<TRI;t++) A[t] = g_G[t*NN + j];
  #pragma unroll
  for (int k=0;k<RNK;k++){
    float s = A[k*(k+1)/2+k];
    #pragma unroll
    for (int m2=0;m2<k;m2++){ float v=A[k*(k+1)/2+m2]; s -= v*v; }
    float lkk = sqrtf(s);
    A[k*(k+1)/2+k]=lkk;
    float inv = 1.0f/lkk;
    #pragma unroll
    for (int i=k+1;i<RNK;i++){
      float t = A[i*(i+1)/2+k];
      #pragma unroll
      for (int m2=0;m2<k;m2++) t -= A[i*(i+1)/2+m2]*A[k*(k+1)/2+m2];
      A[i*(i+1)/2+k]=t*inv;
    }
  }
  #pragma unroll
  for (int jj=0;jj<RNK;jj++){
    A[jj*(jj+1)/2+jj] = 1.0f/A[jj*(jj+1)/2+jj];
    #pragma unroll
    for (int i=jj+1;i<RNK;i++){
      float s=0.f;
      #pragma unroll
      for (int m2=jj;m2<i;m2++) s += A[i*(i+1)/2+m2]*A[m2*(m2+1)/2+jj];
      A[i*(i+1)/2+jj] = -s / A[i*(i+1)/2+i];
    }
  }
  #pragma unroll
  for (int a=0;a<RNK;a++){
    #pragma unroll
    for (int b=0;b<=a;b++){
      float s=0.f;
      #pragma unroll
      for (int m2=a;m2<RNK;m2++) s += A[m2*(m2+1)/2+a]*A[m2*(m2+1)/2+b];
      g_Ginv[(a*(a+1)/2+b)*NN + j] = s;
    }
  }
}

// ---- helpers for column-pair IRLS ----
// dup-packed padded D: sD[r*PDU + k] = pk(v,v); loaded via 5x LDS.128
__device__ __forceinline__ void load_D_dup(u64* sD, const float* D,
                                           int base, int sDr, int sDc, int tid){
  for (int t=tid; t<AROWS*RNK; t+=256){
    int k = t >> 7, r = t & (AROWS-1);
    float v = D[(base+r)*sDr + k*sDc];
    sD[r*PDU+k] = pk(v,v);
  }
}

// load beta pair for columns (jA=2jp, jB=jA+1) into packed negated form
__device__ __forceinline__ void load_nb_pair(u64* nb, const float* beta,
                                             int step, int it, int jA){
  if (it){
    #pragma unroll
    for (int k=0;k<RNK;k++){
      float2 b = *reinterpret_cast<const float2*>(&g_beta1[k*NN + jA]);
      nb[k] = pk(-b.x, -b.y);
    }
  } else if (step==0){
    // beta = g_V, element [k*NN + j]
    #pragma unroll
    for (int k=0;k<RNK;k++){
      float2 b = *reinterpret_cast<const float2*>(&beta[k*NN + jA]);
      nb[k] = pk(-b.x, -b.y);
    }
  } else {
    // beta = g_U, element [j*RNK + k]
    #pragma unroll
    for (int k=0;k<RNK;k++)
      nb[k] = pk(-beta[jA*RNK + k], -beta[(jA+1)*RNK + k]);
  }
}

// ---------------- IRLS pass A: psi^2 partials (column pairs) ----------------
// grid (NN/64, ASEG), block (32,8). Thread owns columns jA=2jp, jB=jA+1.
__global__ void __launch_bounds__(256) k_psiA(const float* __restrict__ Xin, int step, int it){
  __shared__ __align__(16) u64 sD[AROWS*PDU];   // 12 KB
  __shared__ u64 sS[8][33];
  const float* Y    = step ? g_XT : Xin;
  const float* D    = step ? g_V : g_U;
  const int sDr     = step ? 1   : RNK;
  const int sDc     = step ? NN  : 1;
  const float* beta = step ? g_U : g_V;
  int tx=threadIdx.x, ty=threadIdx.y, tid=ty*32+tx;
  int jp = blockIdx.x*32 + tx;
  int jA = 2*jp;
  int base = blockIdx.y * AROWS;
  load_D_dup(sD, D, base, sDr, sDc, tid);
  __syncthreads();
  u64 nb[RNK];
  load_nb_pair(nb, beta, step, it, jA);
  float cc = g_sc[1];
  float sigA, sigB;
  if (it){
    float2 sg = *reinterpret_cast<const float2*>(&g_sigma[jA]);
    sigA = sg.x; sigB = sg.y;
  } else { sigA = sigB = g_sc[4]; }
  float iA = 1.0f/sigA, iB = 1.0f/sigB;
  u64 S2 = pk(0.f,0.f);
  #pragma unroll 4
  for (int r=ty; r<AROWS; r+=8){
    float2 x = *reinterpret_cast<const float2*>(&Y[(size_t)(base+r)*NN + jA]);
    const ulonglong2* dq = reinterpret_cast<const ulonglong2*>(&sD[r*PDU]);
    ulonglong2 q0 = dq[0], q1 = dq[1], q2 = dq[2], q3 = dq[3], q4 = dq[4];
    u64 rr = pk(x.x, x.y);
    rr = fma2(q0.x, nb[0], rr); rr = fma2(q0.y, nb[1], rr);
    rr = fma2(q1.x, nb[2], rr); rr = fma2(q1.y, nb[3], rr);
    rr = fma2(q2.x, nb[4], rr); rr = fma2(q2.y, nb[5], rr);
    rr = fma2(q3.x, nb[6], rr); rr = fma2(q3.y, nb[7], rr);
    rr = fma2(q4.x, nb[8], rr); rr = fma2(q4.y, nb[9], rr);
    float r0,r1; upk(rr,r0,r1);
    r0 = (x.x==0.f) ? 0.f : r0;
    r1 = (x.y==0.f) ? 0.f : r1;
    float p0 = fminf(cc, fmaxf(-cc, r0*iA));
    float p1 = fminf(cc, fmaxf(-cc, r1*iB));
    u64 pp = pk(p0,p1);
    S2 = fma2(pp, pp, S2);
  }
  sS[ty][tx] = S2;
  __syncthreads();
  if (ty==0){
    float tA=0.f, tB=0.f;
    #pragma unroll
    for (int t=0;t<8;t++){ float a,b; upk(sS[t][tx],a,b); tA+=a; tB+=b; }
    *reinterpret_cast<float2*>(&g_Spart[blockIdx.y*NN + jA]) = make_float2(tA,tB);
  }
}

// ---------------- IRLS pass B: inline sigma + rhs partials (column pairs) ----
__global__ void __launch_bounds__(256) k_rhsB(const float* __restrict__ Xin, int step, int it){
  __shared__ __align__(16) u64 sD[AROWS*PDU];   // 12 KB
  __shared__ u64 sR[RNK][8][33];                // 20.6 KB
  const float* Y    = step ? g_XT : Xin;
  const float* D    = step ? g_V : g_U;
  const int sDr     = step ? 1   : RNK;
  const int sDc     = step ? NN  : 1;
  const float* beta = step ? g_U : g_V;
  const float* nobs = step ? g_nobs_row : g_nobs_col;
  int tx=threadIdx.x, ty=threadIdx.y, tid=ty*32+tx;
  int jp = blockIdx.x*32 + tx;
  int jA = 2*jp;
  int base = blockIdx.y * AROWS;
  load_D_dup(sD, D, base, sDr, sDc, tid);
  __syncthreads();
  u64 nb[RNK];
  load_nb_pair(nb, beta, step, it, jA);
  // inline sigma update: sigma_new = sigma_prev * tau^lamda
  float SA=0.f, SB=0.f;
  #pragma unroll
  for (int s=0;s<ASEG;s++){
    float2 sp2 = *reinterpret_cast<const float2*>(&g_Spart[s*NN + jA]);
    SA += sp2.x; SB += sp2.y;
  }
  float al = g_sc[0], lam = g_sc[2], cc = g_sc[1];
  float spA, spB;
  if (it){
    float2 sg = *reinterpret_cast<const float2*>(&g_sigma[jA]);
    spA = sg.x; spB = sg.y;
  } else { spA = spB = g_sc[4]; }
  float2 nb2 = *reinterpret_cast<const float2*>(&nobs[jA]);
  float sigA = spA * powf(sqrtf(SA) / sqrtf(2.0f*nb2.x*al), lam);
  float sigB = spB * powf(sqrtf(SB) / sqrtf(2.0f*nb2.y*al), lam);
  if (it==0 && blockIdx.y==0 && ty==0)
    *reinterpret_cast<float2*>(&g_sigma[jA]) = make_float2(sigA, sigB);
  float csA = cc*sigA, csB = cc*sigB;

  u64 rhs[RNK];
  u64 z = pk(0.f,0.f);
  #pragma unroll
  for (int k=0;k<RNK;k++) rhs[k]=z;
  #pragma unroll 2
  for (int r=ty; r<AROWS; r+=8){
    float2 x = *reinterpret_cast<const float2*>(&Y[(size_t)(base+r)*NN + jA]);
    const ulonglong2* dq = reinterpret_cast<const ulonglong2*>(&sD[r*PDU]);
    ulonglong2 q0 = dq[0], q1 = dq[1], q2 = dq[2], q3 = dq[3], q4 = dq[4];
    u64 rr = pk(x.x, x.y);
    rr = fma2(q0.x, nb[0], rr); rr = fma2(q0.y, nb[1], rr);
    rr = fma2(q1.x, nb[2], rr); rr = fma2(q1.y, nb[3], rr);
    rr = fma2(q2.x, nb[4], rr); rr = fma2(q2.y, nb[5], rr);
    rr = fma2(q3.x, nb[6], rr); rr = fma2(q3.y, nb[7], rr);
    rr = fma2(q4.x, nb[8], rr); rr = fma2(q4.y, nb[9], rr);
    float r0,r1; upk(rr,r0,r1);
    r0 = (x.x==0.f) ? 0.f : r0;
    r1 = (x.y==0.f) ? 0.f : r1;
    float w0 = fminf(csA, fmaxf(-csA, r0));
    float w1 = fminf(csB, fmaxf(-csB, r1));
    u64 ww = pk(w0, w1);
    rhs[0] = fma2(q0.x, ww, rhs[0]); rhs[1] = fma2(q0.y, ww, rhs[1]);
    rhs[2] = fma2(q1.x, ww, rhs[2]); rhs[3] = fma2(q1.y, ww, rhs[3]);
    rhs[4] = fma2(q2.x, ww, rhs[4]); rhs[5] = fma2(q2.y, ww, rhs[5]);
    rhs[6] = fma2(q3.x, ww, rhs[6]); rhs[7] = fma2(q3.y, ww, rhs[7]);
    rhs[8] = fma2(q4.x, ww, rhs[8]); rhs[9] = fma2(q4.y, ww, rhs[9]);
  }
  #pragma unroll
  for (int k=0;k<RNK;k++) sR[k][ty][tx] = rhs[k];
  __syncthreads();
  if (ty==0){
    float* Rout = it ? g_Rpart1 : g_Rpart0;
    #pragma unroll
    for (int k=0;k<RNK;k++){
      float tA=0.f, tB=0.f;
      #pragma unroll
      for (int t=0;t<8;t++){ float a,b; upk(sR[k][t][tx],a,b); tA+=a; tB+=b; }
      *reinterpret_cast<float2*>(&Rout[(blockIdx.y*RNK + k)*NN + jA]) = make_float2(tA,tB);
    }
  }
}

// -------- beta1 = beta0 + mu*Ginv*rhs0 (materialized once, layout [k][j]) ----
__global__ void __launch_bounds__(128) k_beta1(int step){
  int j = blockIdx.x*128 + threadIdx.x;
  const float* beta = step ? g_U : g_V;
  const int sBj = step ? RNK : 1;
  const int sBk = step ? 1   : NN;
  float rr[RNK];
  #pragma unroll
  for (int k=0;k<RNK;k++){
    float s=0.f;
    #pragma unroll
    for (int seg=0;seg<ASEG;seg++) s += g_Rpart0[(seg*RNK + k)*NN + j];
    rr[k]=s;
  }
  float muv = g_sc[3];
  #pragma unroll
  for (int a=0;a<RNK;a++){
    float s=0.f;
    #pragma unroll
    for (int q=0;q<RNK;q++)
      s = fmaf(g_Ginv[triat(a,q)*NN + j], rr[q], s);
    g_beta1[a*NN + j] = beta[j*sBj + a*sBk] + muv*s;
  }
}

// -------- final beta for the step: beta2 = beta1 + mu*Ginv*rhs1 --------------
__global__ void __launch_bounds__(128) k_beta2(int step){
  int j = blockIdx.x*128 + threadIdx.x;
  float* beta = step ? g_U : g_V;
  const int sBj = step ? RNK : 1;
  const int sBk = step ? 1   : NN;
  float rr[RNK];
  #pragma unroll
  for (int k=0;k<RNK;k++){
    float s=0.f;
    #pragma unroll
    for (int seg=0;seg<ASEG;seg++) s += g_Rpart1[(seg*RNK + k)*NN + j];
    rr[k]=s;
  }
  float muv = g_sc[3];
  #pragma unroll
  for (int a=0;a<RNK;a++){
    float s=0.f;
    #pragma unroll
    for (int q=0;q<RNK;q++)
      s = fmaf(g_Ginv[triat(a,q)*NN + j], rr[q], s);
    beta[j*sBj + a*sBk] = g_beta1[a*NN + j] + muv*s;
  }
}

// ---------------- final output: U @ V (float4 over columns) ----------------
__global__ void k_out(float* __restrict__ out){
  int e = blockIdx.x*256 + threadIdx.x;   // group of 4 outputs
  int i = e >> 10;
  int j4 = (e & 1023) * 4;
  float4 s = make_float4(0.f,0.f,0.f,0.f);
  #pragma unroll
  for (int k=0;k<RNK;k++){
    float u = g_U[i*RNK+k];
    float4 v = *reinterpret_cast<const float4*>(&g_V[k*NN + j4]);
    s.x = fmaf(u, v.x, s.x);
    s.y = fmaf(u, v.y, s.y);
    s.z = fmaf(u, v.z, s.z);
    s.w = fmaf(u, v.w, s.w);
  }
  reinterpret_cast<float4*>(out)[e] = s;
}

// ---------------- host driver (graph-capturable: kernel launches only) ----------------
extern "C" void kernel_launch(void* const* d_in, const int* in_sizes, int n_in,
                              void* d_out, int out_size){
  const float *U=0, *V=0, *X=0, *pc=0, *plam=0, *pmu=0, *psg=0;
  int nuv=0, nsc=0;
  for (int i=0;i<n_in;i++){
    if (in_sizes[i] == MM*NN) X = (const float*)d_in[i];
    else if (in_sizes[i] == MM*RNK){ if (nuv==0) U=(const float*)d_in[i]; else V=(const float*)d_in[i]; nuv++; }
    else if (in_sizes[i] == 1){
      if      (nsc==0) pc  =(const float*)d_in[i];
      else if (nsc==1) plam=(const float*)d_in[i];
      else if (nsc==2) pmu =(const float*)d_in[i];
      else if (nsc==3) psg =(const float*)d_in[i];
      nsc++;
    }
  }
  float* out = (float*)d_out;

  k_scalars<<<1,1>>>(pc, plam, pmu, psg);                        // launch 0
  k_copyUV<<<(MM*RNK + 255)/256, 256>>>(U, V);                   // launch 1
  {
    dim3 g(NN/32, MM/32), b(32,8);
    k_transpose<<<g,b>>>(X);                                     // launch 2
  }

  dim3 ggrid(64, GSEG), gblk(32,4);
  dim3 igrid(NN/64, ASEG), iblk(32,8);
  dim3 ngrid(8192/8), nblk(32,8);
  for (int layer=0; layer<N_LAYERS; layer++){
    for (int step=0; step<2; step++){   // 0: V-step, 1: U-step
      k_gram<<<ggrid, gblk>>>(step);
      if (layer==0 && step==0) k_nobs<<<ngrid, nblk>>>();
      k_gred<<<(TRI*NN)/256, 256>>>();
      k_ginv<<<NN/64, 64>>>();
      k_psiA<<<igrid, iblk>>>(X, step, 0);
      k_rhsB<<<igrid, iblk>>>(X, step, 0);
      k_beta1<<<NN/128, 128>>>(step);
      k_psiA<<<igrid, iblk>>>(X, step, 1);
      k_rhsB<<<igrid, iblk>>>(X, step, 1);
      k_beta2<<<NN/128, 128>>>(step);
    }
  }
  k_out<<<(MM*NN/4)/256, 256>>>(out);
}